// round 1
// baseline (speedup 1.0000x reference)
#include <cuda_runtime.h>
#include <math.h>

// ---------------- problem constants ----------------
constexpr int B_  = 2;
constexpr int S_  = 2048;
constexpr int E_  = 1024;
constexpr int H_  = 16;
constexpr int DK_ = 64;
constexpr int HID_= 4096;
constexpr int M_  = B_ * S_;       // 4096 rows

// ---------------- scratch (device globals; no allocations allowed) --------
__device__ float g_x [M_ * E_];          // post-LN1
__device__ float g_q [H_ * M_ * DK_];    // [h][m][64]
__device__ float g_k [H_ * M_ * DK_];
__device__ float g_v [H_ * M_ * DK_];
__device__ float g_xo[M_ * E_];          // x + attn_out
__device__ float g_y [M_ * E_];          // post-LN2
__device__ float g_h [M_ * HID_];        // FFN hidden

// ---------------- LayerNorm: one block per row of 1024 --------------------
__global__ void ln_kernel(const float* __restrict__ in,
                          const float* __restrict__ w,
                          const float* __restrict__ b,
                          float* __restrict__ out) {
    int row = blockIdx.x;
    int t = threadIdx.x;                      // 256 threads, 4 floats each
    const float4* ip = (const float4*)(in + (size_t)row * E_);
    float4 v = ip[t];
    float s  = v.x + v.y + v.z + v.w;
    float sq = v.x*v.x + v.y*v.y + v.z*v.z + v.w*v.w;
    #pragma unroll
    for (int o = 16; o; o >>= 1) {
        s  += __shfl_xor_sync(0xffffffffu, s,  o);
        sq += __shfl_xor_sync(0xffffffffu, sq, o);
    }
    __shared__ float ss[8], ssq[8];
    __shared__ float mu_s, inv_s;
    if ((t & 31) == 0) { ss[t >> 5] = s; ssq[t >> 5] = sq; }
    __syncthreads();
    if (t < 32) {
        float s2  = (t < 8) ? ss[t]  : 0.f;
        float sq2 = (t < 8) ? ssq[t] : 0.f;
        #pragma unroll
        for (int o = 4; o; o >>= 1) {
            s2  += __shfl_xor_sync(0xffffffffu, s2,  o);
            sq2 += __shfl_xor_sync(0xffffffffu, sq2, o);
        }
        if (t == 0) {
            float mu  = s2 * (1.f / E_);
            float var = sq2 * (1.f / E_) - mu * mu;
            mu_s  = mu;
            inv_s = rsqrtf(var + 1e-5f);
        }
    }
    __syncthreads();
    float mu = mu_s, inv = inv_s;
    float4 wv = ((const float4*)w)[t];
    float4 bv = ((const float4*)b)[t];
    float4 o4;
    o4.x = (v.x - mu) * inv * wv.x + bv.x;
    o4.y = (v.y - mu) * inv * wv.y + bv.y;
    o4.z = (v.z - mu) * inv * wv.z + bv.z;
    o4.w = (v.w - mu) * inv * wv.w + bv.w;
    ((float4*)(out + (size_t)row * E_))[t] = o4;
}

// ---------------- SGEMM: C[M x N] = A[M x K] * B[K x N] (+bias/relu/resid) --
// tile 128x64, BK=16, 256 threads, 8x4 per-thread microtile.
// mode 0: C = acc + bias[col]
// mode 1: C = relu(acc + bias[col])
// mode 2: C = acc + bias[col] + resid[row*N+col]
__global__ void gemm_kernel(const float* __restrict__ A,
                            const float* __restrict__ Bm,
                            float* __restrict__ C,
                            const float* __restrict__ bias,
                            const float* __restrict__ resid,
                            int Kdim, int Ndim,
                            long strideB, long strideC, long strideBias,
                            int mode) {
    int bz = blockIdx.z;
    Bm   += (size_t)bz * strideB;
    C    += (size_t)bz * strideC;
    bias += (size_t)bz * strideBias;
    int bm = blockIdx.y * 128;
    int bn = blockIdx.x * 64;

    __shared__ float As[16][128];
    __shared__ float Bs[16][64];

    int t  = threadIdx.x;
    int ty = t >> 4;        // 0..15 -> 8 rows each
    int tx = t & 15;        // 0..15 -> 4 cols each

    float acc[8][4];
    #pragma unroll
    for (int i = 0; i < 8; i++)
        #pragma unroll
        for (int j = 0; j < 4; j++) acc[i][j] = 0.f;

    for (int k0 = 0; k0 < Kdim; k0 += 16) {
        // A tile: 128 rows x 16 k = 512 float4; 2 per thread
        #pragma unroll
        for (int f = 0; f < 2; f++) {
            int fid = t * 2 + f;
            int row = fid >> 2, kq = fid & 3;
            float4 av = *(const float4*)&A[(size_t)(bm + row) * Kdim + k0 + kq * 4];
            As[kq*4+0][row] = av.x;
            As[kq*4+1][row] = av.y;
            As[kq*4+2][row] = av.z;
            As[kq*4+3][row] = av.w;
        }
        // B tile: 16 x 64 = 256 float4; 1 per thread
        {
            int kk = t >> 4, nq = t & 15;
            *(float4*)&Bs[kk][nq * 4] =
                *(const float4*)&Bm[(size_t)(k0 + kk) * Ndim + bn + nq * 4];
        }
        __syncthreads();
        #pragma unroll
        for (int kk = 0; kk < 16; kk++) {
            float a[8], bb[4];
            *(float4*)&a[0] = *(float4*)&As[kk][ty * 8];
            *(float4*)&a[4] = *(float4*)&As[kk][ty * 8 + 4];
            *(float4*)&bb[0] = *(float4*)&Bs[kk][tx * 4];
            #pragma unroll
            for (int i = 0; i < 8; i++)
                #pragma unroll
                for (int j = 0; j < 4; j++)
                    acc[i][j] = fmaf(a[i], bb[j], acc[i][j]);
        }
        __syncthreads();
    }

    #pragma unroll
    for (int i = 0; i < 8; i++) {
        int row = bm + ty * 8 + i;
        #pragma unroll
        for (int j = 0; j < 4; j++) {
            int col = bn + tx * 4 + j;
            float val = acc[i][j] + bias[col];
            if (mode == 1) val = fmaxf(val, 0.f);
            if (mode == 2) val += resid[(size_t)row * Ndim + col];
            C[(size_t)row * Ndim + col] = val;
        }
    }
}

// ---------------- fused causal attention (flash-style), 64x64 tiles -------
// grid: (S/64 query tiles, H, B); 256 threads.
// thread t: row r = t>>2 (0..63), quad g = t&3 owns score cols g*16..g*16+15
// and output dims g*16..g*16+15.
constexpr int TP = 68;  // padded tile stride (floats), 16B-aligned, bank-shifted

__global__ void attention_kernel(const float* __restrict__ q,
                                 const float* __restrict__ k,
                                 const float* __restrict__ v,
                                 const float* __restrict__ x,
                                 float* __restrict__ xo) {
    extern __shared__ float sm[];
    float* Qs = sm;               // 64 x TP
    float* Ks = sm + 64 * TP;
    float* Vs = sm + 2 * 64 * TP;
    float* Ps = sm + 3 * 64 * TP;

    int qt = blockIdx.x, h = blockIdx.y, b = blockIdx.z;
    int t = threadIdx.x;
    int r = t >> 2, g = t & 3;

    const float* qh = q + ((size_t)h * M_ + (size_t)b * S_ + qt * 64) * DK_;
    const float* kh = k + ((size_t)h * M_ + (size_t)b * S_) * DK_;
    const float* vh = v + ((size_t)h * M_ + (size_t)b * S_) * DK_;

    // load Q tile (64x64, rows contiguous) into padded smem
    for (int i = t; i < 64 * 16; i += 256) {        // 1024 float4
        int row = i >> 4, quad = i & 15;
        *(float4*)&Qs[row * TP + quad * 4] = ((const float4*)qh)[i];
    }

    float m = -INFINITY, l = 0.f;
    float acc[16];
    #pragma unroll
    for (int i = 0; i < 16; i++) acc[i] = 0.f;
    __syncthreads();

    for (int kt = 0; kt <= qt; kt++) {
        const float4* ksrc = (const float4*)(kh + (size_t)kt * 64 * DK_);
        const float4* vsrc = (const float4*)(vh + (size_t)kt * 64 * DK_);
        for (int i = t; i < 64 * 16; i += 256) {
            int row = i >> 4, quad = i & 15;
            *(float4*)&Ks[row * TP + quad * 4] = ksrc[i];
            *(float4*)&Vs[row * TP + quad * 4] = vsrc[i];
        }
        __syncthreads();

        // scores: this thread's 16 columns
        float sc[16];
        #pragma unroll
        for (int i = 0; i < 16; i++) sc[i] = 0.f;
        #pragma unroll
        for (int kk = 0; kk < 64; kk += 4) {
            float4 qv = *(const float4*)&Qs[r * TP + kk];
            #pragma unroll
            for (int cc = 0; cc < 16; cc++) {
                float4 kv = *(const float4*)&Ks[(g * 16 + cc) * TP + kk];
                sc[cc] = fmaf(qv.x, kv.x, sc[cc]);
                sc[cc] = fmaf(qv.y, kv.y, sc[cc]);
                sc[cc] = fmaf(qv.z, kv.z, sc[cc]);
                sc[cc] = fmaf(qv.w, kv.w, sc[cc]);
            }
        }
        // scale + causal mask + tile-row max
        int rg = qt * 64 + r;
        float tmax = -INFINITY;
        #pragma unroll
        for (int cc = 0; cc < 16; cc++) {
            sc[cc] *= 0.125f;                        // 1/sqrt(64)
            int cg = kt * 64 + g * 16 + cc;
            if (cg > rg) sc[cc] = -INFINITY;
            tmax = fmaxf(tmax, sc[cc]);
        }
        tmax = fmaxf(tmax, __shfl_xor_sync(0xffffffffu, tmax, 1));
        tmax = fmaxf(tmax, __shfl_xor_sync(0xffffffffu, tmax, 2));

        float m_new = fmaxf(m, tmax);
        float corr  = __expf(m - m_new);

        float psum = 0.f;
        #pragma unroll
        for (int cc = 0; cc < 16; cc++) {
            float p = __expf(sc[cc] - m_new);
            Ps[r * TP + g * 16 + cc] = p;
            psum += p;
        }
        psum += __shfl_xor_sync(0xffffffffu, psum, 1);
        psum += __shfl_xor_sync(0xffffffffu, psum, 2);
        l = l * corr + psum;
        m = m_new;

        #pragma unroll
        for (int i = 0; i < 16; i++) acc[i] *= corr;
        __syncthreads();                 // Ps fully written

        // O += P(row r, all 64 cols) @ V(col, dims g*16..+15)
        #pragma unroll 4
        for (int c = 0; c < 64; c++) {
            float p = Ps[r * TP + c];
            #pragma unroll
            for (int dd = 0; dd < 16; dd += 4) {
                float4 vv = *(const float4*)&Vs[c * TP + g * 16 + dd];
                acc[dd + 0] = fmaf(p, vv.x, acc[dd + 0]);
                acc[dd + 1] = fmaf(p, vv.y, acc[dd + 1]);
                acc[dd + 2] = fmaf(p, vv.z, acc[dd + 2]);
                acc[dd + 3] = fmaf(p, vv.w, acc[dd + 3]);
            }
        }
        __syncthreads();                 // before next tile overwrites Ks/Vs/Ps
    }

    float inv_l = 1.f / l;
    int sg = qt * 64 + r;
    size_t base = ((size_t)(b * S_ + sg)) * E_ + h * 64 + g * 16;
    #pragma unroll
    for (int dd = 0; dd < 16; dd++)
        xo[base + dd] = x[base + dd] + acc[dd] * inv_l;
}

// ---------------- launcher -------------------------------------------------
extern "C" void kernel_launch(void* const* d_in, const int* in_sizes, int n_in,
                              void* d_out, int out_size) {
    const float* emb   = (const float*)d_in[0];
    const float* Wq    = (const float*)d_in[1];
    const float* bq    = (const float*)d_in[2];
    const float* Wk    = (const float*)d_in[3];
    const float* bk    = (const float*)d_in[4];
    const float* Wv    = (const float*)d_in[5];
    const float* bv    = (const float*)d_in[6];
    const float* ln1_w = (const float*)d_in[7];
    const float* ln1_b = (const float*)d_in[8];
    const float* ln2_w = (const float*)d_in[9];
    const float* ln2_b = (const float*)d_in[10];
    const float* W1    = (const float*)d_in[11];
    const float* b1    = (const float*)d_in[12];
    const float* W2    = (const float*)d_in[13];
    const float* b2    = (const float*)d_in[14];
    float* out = (float*)d_out;

    float *px, *pq, *pk, *pv, *pxo, *py, *ph;
    cudaGetSymbolAddress((void**)&px,  g_x);
    cudaGetSymbolAddress((void**)&pq,  g_q);
    cudaGetSymbolAddress((void**)&pk,  g_k);
    cudaGetSymbolAddress((void**)&pv,  g_v);
    cudaGetSymbolAddress((void**)&pxo, g_xo);
    cudaGetSymbolAddress((void**)&py,  g_y);
    cudaGetSymbolAddress((void**)&ph,  g_h);

    const int ATTN_SMEM = 4 * 64 * TP * (int)sizeof(float);   // 69632 B
    cudaFuncSetAttribute(attention_kernel,
                         cudaFuncAttributeMaxDynamicSharedMemorySize, ATTN_SMEM);

    // LN1
    ln_kernel<<<M_, 256>>>(emb, ln1_w, ln1_b, px);

    // QKV projections: batched over heads (z), per-head [4096x1024]@[1024x64]
    dim3 qkv_grid(1, M_ / 128, H_);
    gemm_kernel<<<qkv_grid, 256>>>(px, Wq, pq, bq, nullptr, E_, DK_,
                                   (long)E_ * DK_, (long)M_ * DK_, DK_, 0);
    gemm_kernel<<<qkv_grid, 256>>>(px, Wk, pk, bk, nullptr, E_, DK_,
                                   (long)E_ * DK_, (long)M_ * DK_, DK_, 0);
    gemm_kernel<<<qkv_grid, 256>>>(px, Wv, pv, bv, nullptr, E_, DK_,
                                   (long)E_ * DK_, (long)M_ * DK_, DK_, 0);

    // fused causal attention + residual (x + o) -> g_xo
    dim3 attn_grid(S_ / 64, H_, B_);
    attention_kernel<<<attn_grid, 256, ATTN_SMEM>>>(pq, pk, pv, px, pxo);

    // LN2
    ln_kernel<<<M_, 256>>>(pxo, ln2_w, ln2_b, py);

    // FFN1: h = relu(y @ W1 + b1)   [4096x1024]@[1024x4096]
    dim3 ffn1_grid(HID_ / 64, M_ / 128, 1);
    gemm_kernel<<<ffn1_grid, 256>>>(py, W1, ph, b1, nullptr, E_, HID_,
                                    0, 0, 0, 1);

    // FFN2: out = y + h @ W2 + b2   [4096x4096]@[4096x1024]
    dim3 ffn2_grid(E_ / 64, M_ / 128, 1);
    gemm_kernel<<<ffn2_grid, 256>>>(ph, W2, out, b2, py, HID_, E_,
                                    0, 0, 0, 2);
}

// round 3
// speedup vs baseline: 5.1340x; 5.1340x over previous
#include <cuda_runtime.h>
#include <cuda_bf16.h>
#include <cstdint>
#include <math.h>

// ---------------- problem constants ----------------
constexpr int B_  = 2;
constexpr int S_  = 2048;
constexpr int E_  = 1024;
constexpr int H_  = 16;
constexpr int DK_ = 64;
constexpr int HID_= 4096;
constexpr int M_  = B_ * S_;       // 4096 rows
constexpr int NQKV_ = 3 * E_;      // 3072 fused qkv output cols
constexpr int QKV_LD = NQKV_;

// ================= PTX helpers (base sm_103 target: mma.sync/ldmatrix/cp.async) ==
__device__ __forceinline__ uint32_t smem_to_u32(const void* p) {
    uint32_t a;
    asm("{ .reg .u64 t; cvta.to.shared.u64 t, %1; cvt.u32.u64 %0, t; }"
        : "=r"(a) : "l"(p));
    return a;
}
__device__ __forceinline__ void mma16816(float* d, const uint32_t* a, const uint32_t* b) {
    asm volatile("mma.sync.aligned.m16n8k16.row.col.f32.bf16.bf16.f32 "
        "{%0,%1,%2,%3}, {%4,%5,%6,%7}, {%8,%9}, {%0,%1,%2,%3};"
        : "+f"(d[0]), "+f"(d[1]), "+f"(d[2]), "+f"(d[3])
        : "r"(a[0]), "r"(a[1]), "r"(a[2]), "r"(a[3]), "r"(b[0]), "r"(b[1]));
}
__device__ __forceinline__ void ldsm_x4(uint32_t* r, uint32_t addr) {
    asm volatile("ldmatrix.sync.aligned.m8n8.x4.shared.b16 {%0,%1,%2,%3}, [%4];"
        : "=r"(r[0]), "=r"(r[1]), "=r"(r[2]), "=r"(r[3]) : "r"(addr));
}
__device__ __forceinline__ void ldsm_x2(uint32_t* r, uint32_t addr) {
    asm volatile("ldmatrix.sync.aligned.m8n8.x2.shared.b16 {%0,%1}, [%2];"
        : "=r"(r[0]), "=r"(r[1]) : "r"(addr));
}
__device__ __forceinline__ void ldsm_x2t(uint32_t* r, uint32_t addr) {
    asm volatile("ldmatrix.sync.aligned.m8n8.x2.trans.shared.b16 {%0,%1}, [%2];"
        : "=r"(r[0]), "=r"(r[1]) : "r"(addr));
}
__device__ __forceinline__ void cp_async16(uint32_t dst, const void* src) {
    asm volatile("cp.async.cg.shared.global [%0], [%1], 16;" :: "r"(dst), "l"(src));
}
__device__ __forceinline__ uint32_t packbf2(float a, float b) {
    __nv_bfloat162 h = __floats2bfloat162_rn(a, b);
    return *(uint32_t*)&h;
}

// ---------------- scratch (device globals) --------------------------------
__device__ __align__(16) float g_x  [M_ * E_];
__device__ __align__(16) float g_xo [M_ * E_];
__device__ __align__(16) float g_y  [M_ * E_];
__device__ __align__(16) float g_qkv[M_ * NQKV_];
__device__ __align__(16) __nv_bfloat16 g_xhi[M_ * E_],  g_xlo[M_ * E_];
__device__ __align__(16) __nv_bfloat16 g_yhi[M_ * E_],  g_ylo[M_ * E_];
__device__ __align__(16) __nv_bfloat16 g_hhi[M_ * HID_], g_hlo[M_ * HID_];
__device__ __align__(16) __nv_bfloat16 g_wqkv_hi[NQKV_ * E_], g_wqkv_lo[NQKV_ * E_];
__device__ __align__(16) __nv_bfloat16 g_w1t_hi[HID_ * E_],   g_w1t_lo[HID_ * E_];
__device__ __align__(16) __nv_bfloat16 g_w2t_hi[E_ * HID_],   g_w2t_lo[E_ * HID_];
__device__ float g_bcat[NQKV_];

// ---------------- transpose + fp32 -> bf16 hi/lo ---------------------------
__global__ void transpose_cvt(const float* __restrict__ in,
                              __nv_bfloat16* __restrict__ ohi,
                              __nv_bfloat16* __restrict__ olo,
                              int R, int C, long inBatch, long outBatch) {
    __shared__ float tile[32][33];
    in  += (size_t)blockIdx.z * inBatch;
    ohi += (size_t)blockIdx.z * outBatch;
    olo += (size_t)blockIdx.z * outBatch;
    int c0 = blockIdx.x * 32, r0 = blockIdx.y * 32;
    int tx = threadIdx.x, ty = threadIdx.y;
    #pragma unroll
    for (int j = 0; j < 4; j++)
        tile[ty + j * 8][tx] = in[(size_t)(r0 + ty + j * 8) * C + c0 + tx];
    __syncthreads();
    #pragma unroll
    for (int j = 0; j < 4; j++) {
        float v = tile[tx][ty + j * 8];
        __nv_bfloat16 hi = __float2bfloat16(v);
        float lo = v - __bfloat162float(hi);
        size_t o = (size_t)(c0 + ty + j * 8) * R + r0 + tx;
        ohi[o] = hi;
        olo[o] = __float2bfloat16(lo);
    }
}

__global__ void bias_cat_kernel(const float* __restrict__ bq,
                                const float* __restrict__ bk,
                                const float* __restrict__ bv,
                                float* __restrict__ bcat) {
    int n = blockIdx.x * 256 + threadIdx.x;
    const float* src = (n < 1024) ? bq : ((n < 2048) ? bk : bv);
    bcat[n] = src[n & 1023];
}

// ---------------- LayerNorm: fp32 out + bf16 hi/lo out ---------------------
__global__ void ln_kernel(const float* __restrict__ in,
                          const float* __restrict__ w,
                          const float* __restrict__ b,
                          float* __restrict__ out,
                          __nv_bfloat16* __restrict__ ohi,
                          __nv_bfloat16* __restrict__ olo) {
    int row = blockIdx.x;
    int t = threadIdx.x;
    const float4* ip = (const float4*)(in + (size_t)row * E_);
    float4 v = ip[t];
    float s  = v.x + v.y + v.z + v.w;
    float sq = v.x*v.x + v.y*v.y + v.z*v.z + v.w*v.w;
    #pragma unroll
    for (int o = 16; o; o >>= 1) {
        s  += __shfl_xor_sync(0xffffffffu, s,  o);
        sq += __shfl_xor_sync(0xffffffffu, sq, o);
    }
    __shared__ float ss[8], ssq[8];
    __shared__ float mu_s, inv_s;
    if ((t & 31) == 0) { ss[t >> 5] = s; ssq[t >> 5] = sq; }
    __syncthreads();
    if (t < 32) {
        float s2  = (t < 8) ? ss[t]  : 0.f;
        float sq2 = (t < 8) ? ssq[t] : 0.f;
        #pragma unroll
        for (int o = 4; o; o >>= 1) {
            s2  += __shfl_xor_sync(0xffffffffu, s2,  o);
            sq2 += __shfl_xor_sync(0xffffffffu, sq2, o);
        }
        if (t == 0) {
            float mu  = s2 * (1.f / E_);
            float var = sq2 * (1.f / E_) - mu * mu;
            mu_s  = mu;
            inv_s = rsqrtf(var + 1e-5f);
        }
    }
    __syncthreads();
    float mu = mu_s, inv = inv_s;
    float4 wv = ((const float4*)w)[t];
    float4 bv = ((const float4*)b)[t];
    float4 o4;
    o4.x = (v.x - mu) * inv * wv.x + bv.x;
    o4.y = (v.y - mu) * inv * wv.y + bv.y;
    o4.z = (v.z - mu) * inv * wv.z + bv.z;
    o4.w = (v.w - mu) * inv * wv.w + bv.w;
    ((float4*)(out + (size_t)row * E_))[t] = o4;
    __nv_bfloat16 h0 = __float2bfloat16(o4.x), h1 = __float2bfloat16(o4.y);
    __nv_bfloat16 h2 = __float2bfloat16(o4.z), h3 = __float2bfloat16(o4.w);
    __nv_bfloat162 hp0; hp0.x = h0; hp0.y = h1;
    __nv_bfloat162 hp1; hp1.x = h2; hp1.y = h3;
    ((__nv_bfloat162*)(ohi + (size_t)row * E_))[2*t]   = hp0;
    ((__nv_bfloat162*)(ohi + (size_t)row * E_))[2*t+1] = hp1;
    __nv_bfloat162 lp0, lp1;
    lp0.x = __float2bfloat16(o4.x - __bfloat162float(h0));
    lp0.y = __float2bfloat16(o4.y - __bfloat162float(h1));
    lp1.x = __float2bfloat16(o4.z - __bfloat162float(h2));
    lp1.y = __float2bfloat16(o4.w - __bfloat162float(h3));
    ((__nv_bfloat162*)(olo + (size_t)row * E_))[2*t]   = lp0;
    ((__nv_bfloat162*)(olo + (size_t)row * E_))[2*t+1] = lp1;
}

// ---------------- HMMA GEMM: C[M,N] = (Ahi+Alo) @ (Bhi+Blo)^T --------------
// A: [M][K] bf16 hi/lo.  B: [N][K] bf16 hi/lo (pre-transposed).
// CTA tile 128x128, 8 warps of 64x32, K chunk 32, double-buffered cp.async.
// mode 0: Cf = acc + bias   | mode 1: relu -> Chi/Clo | mode 2: + bias + resid
constexpr int GSTRIDE_B = 80;            // bytes per smem row (40 bf16)
constexpr int GTILE_B   = 128 * GSTRIDE_B;   // 10240 per array
constexpr int GBUF_B    = 4 * GTILE_B;       // 40960 per buffer
constexpr int GEMM_SMEM = 2 * GBUF_B;        // 81920

__global__ __launch_bounds__(256)
void gemm_mma(const __nv_bfloat16* __restrict__ Ahi, const __nv_bfloat16* __restrict__ Alo,
              const __nv_bfloat16* __restrict__ Bhi, const __nv_bfloat16* __restrict__ Blo,
              const float* __restrict__ bias, const float* __restrict__ resid,
              float* __restrict__ Cf,
              __nv_bfloat16* __restrict__ Chi, __nv_bfloat16* __restrict__ Clo,
              int K, int N, int mode) {
    extern __shared__ char smraw[];
    uint32_t sb = smem_to_u32(smraw);
    int t = threadIdx.x, lane = t & 31, wid = t >> 5;
    int bm = blockIdx.y * 128, bn = blockIdx.x * 128;
    int wm = wid & 1, wn = wid >> 1;

    const __nv_bfloat16* gsrc[4] = {
        Ahi + (size_t)bm * K, Alo + (size_t)bm * K,
        Bhi + (size_t)bn * K, Blo + (size_t)bn * K };

    float acc[4][4][4];
    #pragma unroll
    for (int i = 0; i < 4; i++)
        #pragma unroll
        for (int j = 0; j < 4; j++)
            #pragma unroll
            for (int e = 0; e < 4; e++) acc[i][j][e] = 0.f;

    int nch = K >> 5;

    // ---- load chunk 0 ----
    {
        uint32_t base = sb;
        #pragma unroll
        for (int arr = 0; arr < 4; arr++) {
            uint32_t dst = base + arr * GTILE_B;
            #pragma unroll
            for (int f = 0; f < 2; f++) {
                int idx = t + f * 256;
                int row = idx >> 2, seg = idx & 3;
                cp_async16(dst + row * GSTRIDE_B + seg * 16,
                           gsrc[arr] + (size_t)row * K + seg * 8);
            }
        }
        asm volatile("cp.async.commit_group;");
    }

    for (int c = 0; c < nch; c++) {
        if (c + 1 < nch) {
            int k0 = (c + 1) << 5;
            uint32_t base = sb + ((c + 1) & 1) * GBUF_B;
            #pragma unroll
            for (int arr = 0; arr < 4; arr++) {
                uint32_t dst = base + arr * GTILE_B;
                #pragma unroll
                for (int f = 0; f < 2; f++) {
                    int idx = t + f * 256;
                    int row = idx >> 2, seg = idx & 3;
                    cp_async16(dst + row * GSTRIDE_B + seg * 16,
                               gsrc[arr] + (size_t)row * K + k0 + seg * 8);
                }
            }
            asm volatile("cp.async.commit_group;");
            asm volatile("cp.async.wait_group 1;");
        } else {
            asm volatile("cp.async.wait_group 0;");
        }
        __syncthreads();

        uint32_t base = sb + (c & 1) * GBUF_B;
        uint32_t aHiB = base;
        uint32_t aLoB = base + GTILE_B;
        uint32_t bHiB = base + 2 * GTILE_B;
        uint32_t bLoB = base + 3 * GTILE_B;

        #pragma unroll
        for (int ks = 0; ks < 2; ks++) {
            int k0 = ks * 16;
            int arow = wm * 64 + (lane & 7) + ((lane >> 3) & 1) * 8;
            int acol = k0 + (lane >> 4) * 8;
            int brow = wn * 32 + (lane & 7);
            int bcol = k0 + ((lane >> 3) & 1) * 8;

            uint32_t ah[4][4];
            #pragma unroll
            for (int mt = 0; mt < 4; mt++)
                ldsm_x4(ah[mt], aHiB + (arow + mt * 16) * GSTRIDE_B + acol * 2);
            #pragma unroll
            for (int nt = 0; nt < 4; nt++) {
                uint32_t bh[2], bl[2];
                ldsm_x2(bh, bHiB + (brow + nt * 8) * GSTRIDE_B + bcol * 2);
                ldsm_x2(bl, bLoB + (brow + nt * 8) * GSTRIDE_B + bcol * 2);
                #pragma unroll
                for (int mt = 0; mt < 4; mt++) {
                    mma16816(acc[mt][nt], ah[mt], bh);
                    mma16816(acc[mt][nt], ah[mt], bl);
                }
            }
            uint32_t al[4][4];
            #pragma unroll
            for (int mt = 0; mt < 4; mt++)
                ldsm_x4(al[mt], aLoB + (arow + mt * 16) * GSTRIDE_B + acol * 2);
            #pragma unroll
            for (int nt = 0; nt < 4; nt++) {
                uint32_t bh[2];
                ldsm_x2(bh, bHiB + (brow + nt * 8) * GSTRIDE_B + bcol * 2);
                #pragma unroll
                for (int mt = 0; mt < 4; mt++)
                    mma16816(acc[mt][nt], al[mt], bh);
            }
        }
        __syncthreads();
    }

    // ---- epilogue ----
    int r = lane >> 2, q2 = (lane & 3) * 2;
    #pragma unroll
    for (int mt = 0; mt < 4; mt++) {
        int row0 = bm + wm * 64 + mt * 16 + r;
        #pragma unroll
        for (int nt = 0; nt < 4; nt++) {
            int col = bn + wn * 32 + nt * 8 + q2;
            float b0 = bias[col], b1 = bias[col + 1];
            float v0 = acc[mt][nt][0] + b0, v1 = acc[mt][nt][1] + b1;
            float v2 = acc[mt][nt][2] + b0, v3 = acc[mt][nt][3] + b1;
            size_t gi0 = (size_t)row0 * N + col;
            size_t gi1 = gi0 + (size_t)8 * N;
            if (mode == 0) {
                *(float2*)(Cf + gi0) = make_float2(v0, v1);
                *(float2*)(Cf + gi1) = make_float2(v2, v3);
            } else if (mode == 1) {
                v0 = fmaxf(v0, 0.f); v1 = fmaxf(v1, 0.f);
                v2 = fmaxf(v2, 0.f); v3 = fmaxf(v3, 0.f);
                __nv_bfloat162 h0; h0.x = __float2bfloat16(v0); h0.y = __float2bfloat16(v1);
                __nv_bfloat162 h1; h1.x = __float2bfloat16(v2); h1.y = __float2bfloat16(v3);
                *(__nv_bfloat162*)(Chi + gi0) = h0;
                *(__nv_bfloat162*)(Chi + gi1) = h1;
                __nv_bfloat162 l0, l1;
                l0.x = __float2bfloat16(v0 - __bfloat162float(h0.x));
                l0.y = __float2bfloat16(v1 - __bfloat162float(h0.y));
                l1.x = __float2bfloat16(v2 - __bfloat162float(h1.x));
                l1.y = __float2bfloat16(v3 - __bfloat162float(h1.y));
                *(__nv_bfloat162*)(Clo + gi0) = l0;
                *(__nv_bfloat162*)(Clo + gi1) = l1;
            } else {
                float2 r0 = *(const float2*)(resid + gi0);
                float2 r1 = *(const float2*)(resid + gi1);
                *(float2*)(Cf + gi0) = make_float2(v0 + r0.x, v1 + r0.y);
                *(float2*)(Cf + gi1) = make_float2(v2 + r1.x, v3 + r1.y);
            }
        }
    }
}

// ---------------- HMMA flash attention ------------------------------------
// CTA: 128 q rows (8 warps x 16 rows), kv tiles of 64. grid (16, H, B).
constexpr int AQ_STRIDE = 144;   // bytes: 72 bf16 per row
constexpr int AOFF_QHI = 0;
constexpr int AOFF_QLO = 128 * AQ_STRIDE;          // 18432
constexpr int AOFF_KHI = 2 * 128 * AQ_STRIDE;      // 36864
constexpr int AOFF_KLO = AOFF_KHI + 64 * AQ_STRIDE;
constexpr int AOFF_VHI = AOFF_KLO + 64 * AQ_STRIDE;
constexpr int AOFF_VLO = AOFF_VHI + 64 * AQ_STRIDE;
constexpr int ATTN_SMEM = AOFF_VLO + 64 * AQ_STRIDE;   // 73728

__global__ __launch_bounds__(256)
void attn_mma(const float* __restrict__ qkv,
              const float* __restrict__ x,
              float* __restrict__ xo) {
    extern __shared__ char smraw[];
    uint32_t sb = smem_to_u32(smraw);
    int qt = blockIdx.x, h = blockIdx.y, b = blockIdx.z;
    int t = threadIdx.x, lane = t & 31, wid = t >> 5;

    // ---- load + scale + split Q tile (128 x 64) ----
    const float* qsrc = qkv + (size_t)(b * S_ + qt * 128) * QKV_LD + h * 64;
    #pragma unroll
    for (int f = 0; f < 8; f++) {
        int i = t + f * 256;
        int row = i >> 4, quad = i & 15;
        float4 v = *(const float4*)(qsrc + (size_t)row * QKV_LD + quad * 4);
        v.x *= 0.125f; v.y *= 0.125f; v.z *= 0.125f; v.w *= 0.125f;
        __nv_bfloat16 h0 = __float2bfloat16(v.x), h1 = __float2bfloat16(v.y);
        __nv_bfloat16 h2 = __float2bfloat16(v.z), h3 = __float2bfloat16(v.w);
        uint32_t off = row * AQ_STRIDE + quad * 8;
        __nv_bfloat162 p0; p0.x = h0; p0.y = h1;
        __nv_bfloat162 p1; p1.x = h2; p1.y = h3;
        *(__nv_bfloat162*)(smraw + AOFF_QHI + off)     = p0;
        *(__nv_bfloat162*)(smraw + AOFF_QHI + off + 4) = p1;
        __nv_bfloat162 l0, l1;
        l0.x = __float2bfloat16(v.x - __bfloat162float(h0));
        l0.y = __float2bfloat16(v.y - __bfloat162float(h1));
        l1.x = __float2bfloat16(v.z - __bfloat162float(h2));
        l1.y = __float2bfloat16(v.w - __bfloat162float(h3));
        *(__nv_bfloat162*)(smraw + AOFF_QLO + off)     = l0;
        *(__nv_bfloat162*)(smraw + AOFF_QLO + off + 4) = l1;
    }

    float o[8][4];
    #pragma unroll
    for (int i = 0; i < 8; i++)
        #pragma unroll
        for (int j = 0; j < 4; j++) o[i][j] = 0.f;
    float m0 = -INFINITY, m1 = -INFINITY, l0 = 0.f, l1 = 0.f;

    const float* ksrc0 = qkv + (size_t)(b * S_) * QKV_LD + 1024 + h * 64;
    const float* vsrc0 = ksrc0 + 1024;

    int r = lane >> 2, q2 = (lane & 3) * 2;
    int grow0 = qt * 128 + wid * 16 + r;
    int grow1 = grow0 + 8;

    int nkt = 2 * qt + 2;
    for (int kt = 0; kt < nkt; kt++) {
        __syncthreads();    // previous iteration's reads done before overwrite
        // ---- load + split K,V tiles (64 x 64 each) ----
        const float* ks = ksrc0 + (size_t)(kt * 64) * QKV_LD;
        const float* vs = vsrc0 + (size_t)(kt * 64) * QKV_LD;
        #pragma unroll
        for (int f = 0; f < 4; f++) {
            int i = t + f * 256;
            int row = i >> 4, quad = i & 15;
            uint32_t off = row * AQ_STRIDE + quad * 8;
            float4 v = *(const float4*)(ks + (size_t)row * QKV_LD + quad * 4);
            __nv_bfloat16 h0 = __float2bfloat16(v.x), h1 = __float2bfloat16(v.y);
            __nv_bfloat16 h2 = __float2bfloat16(v.z), h3 = __float2bfloat16(v.w);
            __nv_bfloat162 p0, p1, e0, e1;
            p0.x = h0; p0.y = h1; p1.x = h2; p1.y = h3;
            e0.x = __float2bfloat16(v.x - __bfloat162float(h0));
            e0.y = __float2bfloat16(v.y - __bfloat162float(h1));
            e1.x = __float2bfloat16(v.z - __bfloat162float(h2));
            e1.y = __float2bfloat16(v.w - __bfloat162float(h3));
            *(__nv_bfloat162*)(smraw + AOFF_KHI + off)     = p0;
            *(__nv_bfloat162*)(smraw + AOFF_KHI + off + 4) = p1;
            *(__nv_bfloat162*)(smraw + AOFF_KLO + off)     = e0;
            *(__nv_bfloat162*)(smraw + AOFF_KLO + off + 4) = e1;
            v = *(const float4*)(vs + (size_t)row * QKV_LD + quad * 4);
            h0 = __float2bfloat16(v.x); h1 = __float2bfloat16(v.y);
            h2 = __float2bfloat16(v.z); h3 = __float2bfloat16(v.w);
            p0.x = h0; p0.y = h1; p1.x = h2; p1.y = h3;
            e0.x = __float2bfloat16(v.x - __bfloat162float(h0));
            e0.y = __float2bfloat16(v.y - __bfloat162float(h1));
            e1.x = __float2bfloat16(v.z - __bfloat162float(h2));
            e1.y = __float2bfloat16(v.w - __bfloat162float(h3));
            *(__nv_bfloat162*)(smraw + AOFF_VHI + off)     = p0;
            *(__nv_bfloat162*)(smraw + AOFF_VHI + off + 4) = p1;
            *(__nv_bfloat162*)(smraw + AOFF_VLO + off)     = e0;
            *(__nv_bfloat162*)(smraw + AOFF_VLO + off + 4) = e1;
        }
        __syncthreads();

        // ---- scores S = Q K^T (hi/lo, 3 passes) ----
        float s[8][4];
        #pragma unroll
        for (int i = 0; i < 8; i++)
            #pragma unroll
            for (int j = 0; j < 4; j++) s[i][j] = 0.f;

        int arow = wid * 16 + (lane & 7) + ((lane >> 3) & 1) * 8;
        int brow = lane & 7;
        #pragma unroll
        for (int ksIdx = 0; ksIdx < 4; ksIdx++) {
            int k0 = ksIdx * 16;
            int acol = k0 + (lane >> 4) * 8;
            int bcol = k0 + ((lane >> 3) & 1) * 8;
            uint32_t qh[4], ql[4];
            ldsm_x4(qh, sb + AOFF_QHI + arow * AQ_STRIDE + acol * 2);
            ldsm_x4(ql, sb + AOFF_QLO + arow * AQ_STRIDE + acol * 2);
            #pragma unroll
            for (int nt = 0; nt < 8; nt++) {
                uint32_t kh[2], kl[2];
                ldsm_x2(kh, sb + AOFF_KHI + (nt * 8 + brow) * AQ_STRIDE + bcol * 2);
                ldsm_x2(kl, sb + AOFF_KLO + (nt * 8 + brow) * AQ_STRIDE + bcol * 2);
                mma16816(s[nt], qh, kh);
                mma16816(s[nt], ql, kh);
                mma16816(s[nt], qh, kl);
            }
        }

        // ---- causal mask (only needed on diagonal tiles) ----
        if (kt >= 2 * qt) {
            #pragma unroll
            for (int nt = 0; nt < 8; nt++) {
                int gc = kt * 64 + nt * 8 + q2;
                if (gc > grow0)     s[nt][0] = -INFINITY;
                if (gc + 1 > grow0) s[nt][1] = -INFINITY;
                if (gc > grow1)     s[nt][2] = -INFINITY;
                if (gc + 1 > grow1) s[nt][3] = -INFINITY;
            }
        }

        // ---- online softmax (rows r, r+8 per thread; quad reduce) ----
        float mx0 = -INFINITY, mx1 = -INFINITY;
        #pragma unroll
        for (int nt = 0; nt < 8; nt++) {
            mx0 = fmaxf(mx0, fmaxf(s[nt][0], s[nt][1]));
            mx1 = fmaxf(mx1, fmaxf(s[nt][2], s[nt][3]));
        }
        mx0 = fmaxf(mx0, __shfl_xor_sync(0xffffffffu, mx0, 1));
        mx0 = fmaxf(mx0, __shfl_xor_sync(0xffffffffu, mx0, 2));
        mx1 = fmaxf(mx1, __shfl_xor_sync(0xffffffffu, mx1, 1));
        mx1 = fmaxf(mx1, __shfl_xor_sync(0xffffffffu, mx1, 2));
        float mn0 = fmaxf(m0, mx0), mn1 = fmaxf(m1, mx1);
        float c0 = __expf(m0 - mn0), c1 = __expf(m1 - mn1);
        float ps0 = 0.f, ps1 = 0.f;
        #pragma unroll
        for (int nt = 0; nt < 8; nt++) {
            s[nt][0] = __expf(s[nt][0] - mn0);
            s[nt][1] = __expf(s[nt][1] - mn0);
            s[nt][2] = __expf(s[nt][2] - mn1);
            s[nt][3] = __expf(s[nt][3] - mn1);
            ps0 += s[nt][0] + s[nt][1];
            ps1 += s[nt][2] + s[nt][3];
        }
        ps0 += __shfl_xor_sync(0xffffffffu, ps0, 1);
        ps0 += __shfl_xor_sync(0xffffffffu, ps0, 2);
        ps1 += __shfl_xor_sync(0xffffffffu, ps1, 1);
        ps1 += __shfl_xor_sync(0xffffffffu, ps1, 2);
        l0 = l0 * c0 + ps0;
        l1 = l1 * c1 + ps1;
        m0 = mn0; m1 = mn1;
        #pragma unroll
        for (int dt = 0; dt < 8; dt++) {
            o[dt][0] *= c0; o[dt][1] *= c0;
            o[dt][2] *= c1; o[dt][3] *= c1;
        }

        // ---- O += P @ V (P from registers; V hi/lo via ldmatrix.trans) ----
        #pragma unroll
        for (int ksIdx = 0; ksIdx < 4; ksIdx++) {
            uint32_t a[4];
            a[0] = packbf2(s[2*ksIdx][0],   s[2*ksIdx][1]);
            a[1] = packbf2(s[2*ksIdx][2],   s[2*ksIdx][3]);
            a[2] = packbf2(s[2*ksIdx+1][0], s[2*ksIdx+1][1]);
            a[3] = packbf2(s[2*ksIdx+1][2], s[2*ksIdx+1][3]);
            int vrow = ksIdx * 16 + (lane & 15);
            #pragma unroll
            for (int dt = 0; dt < 8; dt++) {
                uint32_t vh[2], vl[2];
                ldsm_x2t(vh, sb + AOFF_VHI + vrow * AQ_STRIDE + dt * 16);
                ldsm_x2t(vl, sb + AOFF_VLO + vrow * AQ_STRIDE + dt * 16);
                mma16816(o[dt], a, vh);
                mma16816(o[dt], a, vl);
            }
        }
    }

    // ---- epilogue: o/l + residual ----
    float il0 = 1.f / l0, il1 = 1.f / l1;
    int row0 = b * S_ + qt * 128 + wid * 16 + r;
    int row1 = row0 + 8;
    #pragma unroll
    for (int dt = 0; dt < 8; dt++) {
        int col = h * 64 + dt * 8 + q2;
        size_t gi0 = (size_t)row0 * E_ + col;
        size_t gi1 = (size_t)row1 * E_ + col;
        float2 x0 = *(const float2*)(x + gi0);
        float2 x1 = *(const float2*)(x + gi1);
        *(float2*)(xo + gi0) = make_float2(x0.x + o[dt][0] * il0,
                                           x0.y + o[dt][1] * il0);
        *(float2*)(xo + gi1) = make_float2(x1.x + o[dt][2] * il1,
                                           x1.y + o[dt][3] * il1);
    }
}

// ---------------- launcher -------------------------------------------------
extern "C" void kernel_launch(void* const* d_in, const int* in_sizes, int n_in,
                              void* d_out, int out_size) {
    const float* emb   = (const float*)d_in[0];
    const float* Wq    = (const float*)d_in[1];
    const float* bq    = (const float*)d_in[2];
    const float* Wk    = (const float*)d_in[3];
    const float* bk    = (const float*)d_in[4];
    const float* Wv    = (const float*)d_in[5];
    const float* bv    = (const float*)d_in[6];
    const float* ln1_w = (const float*)d_in[7];
    const float* ln1_b = (const float*)d_in[8];
    const float* ln2_w = (const float*)d_in[9];
    const float* ln2_b = (const float*)d_in[10];
    const float* W1    = (const float*)d_in[11];
    const float* b1    = (const float*)d_in[12];
    const float* W2    = (const float*)d_in[13];
    const float* b2    = (const float*)d_in[14];
    float* out = (float*)d_out;

    float *px, *pxo, *py, *pqkv, *pbcat;
    __nv_bfloat16 *pxhi, *pxlo, *pyhi, *pylo, *phhi, *phlo;
    __nv_bfloat16 *pwqh, *pwql, *pw1h, *pw1l, *pw2h, *pw2l;
    cudaGetSymbolAddress((void**)&px,   g_x);
    cudaGetSymbolAddress((void**)&pxo,  g_xo);
    cudaGetSymbolAddress((void**)&py,   g_y);
    cudaGetSymbolAddress((void**)&pqkv, g_qkv);
    cudaGetSymbolAddress((void**)&pbcat,g_bcat);
    cudaGetSymbolAddress((void**)&pxhi, g_xhi);
    cudaGetSymbolAddress((void**)&pxlo, g_xlo);
    cudaGetSymbolAddress((void**)&pyhi, g_yhi);
    cudaGetSymbolAddress((void**)&pylo, g_ylo);
    cudaGetSymbolAddress((void**)&phhi, g_hhi);
    cudaGetSymbolAddress((void**)&phlo, g_hlo);
    cudaGetSymbolAddress((void**)&pwqh, g_wqkv_hi);
    cudaGetSymbolAddress((void**)&pwql, g_wqkv_lo);
    cudaGetSymbolAddress((void**)&pw1h, g_w1t_hi);
    cudaGetSymbolAddress((void**)&pw1l, g_w1t_lo);
    cudaGetSymbolAddress((void**)&pw2h, g_w2t_hi);
    cudaGetSymbolAddress((void**)&pw2l, g_w2t_lo);

    cudaFuncSetAttribute(gemm_mma,
                         cudaFuncAttributeMaxDynamicSharedMemorySize, GEMM_SMEM);
    cudaFuncSetAttribute(attn_mma,
                         cudaFuncAttributeMaxDynamicSharedMemorySize, ATTN_SMEM);

    dim3 tb(32, 8);
    transpose_cvt<<<dim3(2, 32, 16), tb>>>(Wq, pwqh,           pwql,           E_, DK_, (long)E_*DK_, (long)DK_*E_);
    transpose_cvt<<<dim3(2, 32, 16), tb>>>(Wk, pwqh + 1024*E_, pwql + 1024*E_, E_, DK_, (long)E_*DK_, (long)DK_*E_);
    transpose_cvt<<<dim3(2, 32, 16), tb>>>(Wv, pwqh + 2048*E_, pwql + 2048*E_, E_, DK_, (long)E_*DK_, (long)DK_*E_);
    transpose_cvt<<<dim3(HID_/32, E_/32, 1), tb>>>(W1, pw1h, pw1l, E_, HID_, 0, 0);
    transpose_cvt<<<dim3(E_/32, HID_/32, 1), tb>>>(W2, pw2h, pw2l, HID_, E_, 0, 0);
    bias_cat_kernel<<<NQKV_/256, 256>>>(bq, bk, bv, pbcat);

    // LN1 -> x fp32 + hi/lo
    ln_kernel<<<M_, 256>>>(emb, ln1_w, ln1_b, px, pxhi, pxlo);

    // fused QKV: [4096 x 3072]
    gemm_mma<<<dim3(NQKV_/128, M_/128), 256, GEMM_SMEM>>>(
        pxhi, pxlo, pwqh, pwql, pbcat, nullptr, pqkv, nullptr, nullptr,
        E_, NQKV_, 0);

    // attention + residual -> g_xo
    attn_mma<<<dim3(S_/128, H_, B_), 256, ATTN_SMEM>>>(pqkv, px, pxo);

    // LN2 -> y fp32 + hi/lo
    ln_kernel<<<M_, 256>>>(pxo, ln2_w, ln2_b, py, pyhi, pylo);

    // FFN1: h = relu(y @ W1 + b1) -> bf16 hi/lo
    gemm_mma<<<dim3(HID_/128, M_/128), 256, GEMM_SMEM>>>(
        pyhi, pylo, pw1h, pw1l, b1, nullptr, nullptr, phhi, phlo,
        E_, HID_, 1);

    // FFN2: out = y + h @ W2 + b2
    gemm_mma<<<dim3(E_/128, M_/128), 256, GEMM_SMEM>>>(
        phhi, phlo, pw2h, pw2l, b2, py, out, nullptr, nullptr,
        HID_, E_, 2);
}